// round 14
// baseline (speedup 1.0000x reference)
#include <cuda_runtime.h>
#include <cuda_fp16.h>

// Bilateral filter 9x9, sigma_s=3, sigma_r=0.1, reflect padding, 4096x4096 fp32.
//
// w = exp2( -K2*(win-c)^2 + Ls(dx,dy) ),  K2 = 50*log2(e)
// expanded: u = (-K2*win + a)*win + b;  g = u + Ls   (Ls as FADD-immediate)
//   a = 2*K2*c, b = -K2*c^2
//
// Round-14: R13 showed ptxas hoists the 60 per-pixel (b+Ls) constants into
// registers (demand ~80 -> spills at any cap <80 -> occupancy stuck at 36%).
// Fix: apply Ls as a separate FADD with an IMMEDIATE constant (+1 op/tap,
// zero registers). Demand drops to ~45 -> (128,8) cap (64 regs) is now safe:
// occ 50%, no spill.
//
// Geometry unchanged from best lineage: 2x2 px/thread; window row union
// (10 floats) = 5 aligned LDS.64 shared by 4 pixels; f16x2 ex2 pairing with
// zero wasted taps. 40.5 MUFU/px.

#define IMG_H 4096
#define IMG_W 4096
#define RAD 4
#define BX 32
#define BY 4
#define PX 2
#define PY 2
#define TILE_PW (BX * PX)          // 64 pixel cols per block
#define TILE_PH (BY * PY)          // 8 pixel rows per block
#define TW (TILE_PW + 2*RAD)       // 72 floats/row (288B, 8B-aligned stride)
#define TH (TILE_PH + 2*RAD)       // 16 rows

#define K2F 72.13475204444817f                    /* 50 * log2(e) */
#define LSC (1.4426950408889634f / 18.0f)

// one MUFU op, two exp2's (f32 in/out, f16 internally)
__device__ __forceinline__ float2 ex2pair(float a0, float a1) {
    __half2 h = __floats2half2_rn(a0, a1);
    unsigned hu = *reinterpret_cast<unsigned*>(&h);
    unsigned wu;
    asm("ex2.approx.f16x2 %0, %1;" : "=r"(wu) : "r"(hu));
    __half2 w = *reinterpret_cast<__half2*>(&wu);
    return make_float2(__low2float(w), __high2float(w));
}

__global__ __launch_bounds__(BX * BY, 8)
void bilateral_kernel(const float* __restrict__ img, float* __restrict__ out) {
    __shared__ __align__(16) float tile[TH][TW];

    const int tx = threadIdx.x;
    const int ty = threadIdx.y;
    const int bx0 = blockIdx.x * TILE_PW;
    const int by0 = blockIdx.y * TILE_PH;

    // ---- tile fill: strided, reflect at edges ----
    #pragma unroll
    for (int r = ty; r < TH; r += BY) {
        int gy = by0 + r - RAD;
        gy = (gy < 0) ? -gy : ((gy >= IMG_H) ? (2 * IMG_H - 2 - gy) : gy);
        const float* __restrict__ src = img + (size_t)gy * IMG_W;
        #pragma unroll
        for (int c = tx; c < TW; c += BX) {
            int gx = bx0 + c - RAD;
            gx = (gx < 0) ? -gx : ((gx >= IMG_W) ? (2 * IMG_W - 2 - gx) : gx);
            tile[r][c] = src[gx];
        }
    }
    __syncthreads();

    const int cb  = tx * PX;   // even -> aligned float2 window loads
    const int py0 = ty * PY;

    // pixels p = j*2+i, center tile[py0+4+j][cb+4+i]
    float a[4], b[4], num[4], den[4];
    #pragma unroll
    for (int j = 0; j < PY; j++) {
        #pragma unroll
        for (int i = 0; i < PX; i++) {
            const float c = tile[py0 + RAD + j][cb + RAD + i];
            const int p = j * 2 + i;
            a[p] = 2.0f * K2F * c;
            b[p] = -K2F * c * c;
            num[p] = 0.f;
            den[p] = 0.f;
        }
    }

    // window rows r = 0..9; px-row j active iff j <= r <= j+8
    #pragma unroll
    for (int r = 0; r < 10; r++) {
        // 10-float union row as 5 aligned LDS.64
        float f[10];
        const float2* __restrict__ rp =
            reinterpret_cast<const float2*>(&tile[py0 + r][cb]);
        #pragma unroll
        for (int q = 0; q < 5; q++) {
            const float2 v = rp[q];
            f[2 * q]     = v.x;
            f[2 * q + 1] = v.y;
        }

        if (r == 0 || r == 9) {
            // one pixel row active -> pair HORIZONTALLY (p0=left, p1=right)
            const int p0 = (r == 0) ? 0 : 2;
            const int p1 = p0 + 1;
            #pragma unroll
            for (int k = 0; k < 9; k++) {
                const float Ls = -(float)((k - 4) * (k - 4) + 16) * LSC; // imm
                const float w0 = f[k];
                const float w1 = f[k + 1];
                const float u0 = fmaf(w0, fmaf(-K2F, w0, a[p0]), b[p0]);
                const float u1 = fmaf(w1, fmaf(-K2F, w1, a[p1]), b[p1]);
                const float2 w = ex2pair(u0 + Ls, u1 + Ls);   // FADD-imm, 1 MUFU
                num[p0] = fmaf(w.x, w0, num[p0]);
                den[p0] += w.x;
                num[p1] = fmaf(w.y, w1, num[p1]);
                den[p1] += w.y;
            }
        } else {
            // both pixel rows active -> pair VERTICALLY per column (shared win)
            const int dq0 = (r - 4) * (r - 4);   // compile-time
            const int dq1 = (r - 5) * (r - 5);
            #pragma unroll
            for (int i = 0; i < PX; i++) {
                const int pT = i;
                const int pB = 2 + i;
                #pragma unroll
                for (int k = 0; k < 9; k++) {
                    const float win = f[i + k];
                    const int   kq  = (k - 4) * (k - 4);
                    const float Ls0 = -(float)(kq + dq0) * LSC;  // imm
                    const float Ls1 = -(float)(kq + dq1) * LSC;  // imm
                    const float u0 = fmaf(win, fmaf(-K2F, win, a[pT]), b[pT]);
                    const float u1 = fmaf(win, fmaf(-K2F, win, a[pB]), b[pB]);
                    const float2 w = ex2pair(u0 + Ls0, u1 + Ls1); // FADD-imm x2
                    num[pT] = fmaf(w.x, win, num[pT]);
                    den[pT] += w.x;
                    num[pB] = fmaf(w.y, win, num[pB]);
                    den[pB] += w.y;
                }
            }
        }
    }

    // 2x2 output, one aligned float2 store per pixel row
    #pragma unroll
    for (int j = 0; j < PY; j++) {
        float2 o;
        o.x = __fdividef(num[j * 2 + 0], den[j * 2 + 0]);
        o.y = __fdividef(num[j * 2 + 1], den[j * 2 + 1]);
        *reinterpret_cast<float2*>(
            &out[(size_t)(by0 + py0 + j) * IMG_W + bx0 + cb]) = o;
    }
}

extern "C" void kernel_launch(void* const* d_in, const int* in_sizes, int n_in,
                              void* d_out, int out_size) {
    const float* img = (const float*)d_in[0];
    float* out = (float*)d_out;
    dim3 block(BX, BY);
    dim3 grid(IMG_W / TILE_PW, IMG_H / TILE_PH);
    bilateral_kernel<<<grid, block>>>(img, out);
}

// round 15
// speedup vs baseline: 1.1816x; 1.1816x over previous
#include <cuda_runtime.h>
#include <cuda_fp16.h>

// Bilateral filter 9x9, sigma_s=3, sigma_r=0.1, reflect padding, 4096x4096 fp32.
//
// Round-15: full f16x2 tap pipeline in (win-c) difference form.
//   w = Swk(kq) * Swr(dq) * exp2(-K2*d^2),  d = win - c  (all f16x2, packed)
//   out = c + sum(w*d)/sum(w)    <- c-offset form suppresses all f16
//                                   accumulation error by (out-c) ~ 0.05
// Spatial weight separable: exp(-(kq+dq)/18) = Swk * Swr -> only 14 half2
// constants, shared by ALL pixels (kills the 60-reg btap hoisting that
// pinned R11-R14 at ~313us).
// Tile stored as duplicated half2 (v,v): LDS.64 gives (win,win) pairs free.
// Per vertical pair: HSUB2,HMUL2,HMUL2,MUFU,HMUL2,HMUL2,HFMA2,HADD2 = 8 ops
// -> 4 issues/pixel-tap vs 6 for the f32 form. 40.5 MUFU/px unchanged.

#define IMG_H 4096
#define IMG_W 4096
#define RAD 4
#define BX 32
#define BY 4
#define PX 2
#define PY 2
#define TILE_PW (BX * PX)          // 64 pixel cols per block
#define TILE_PH (BY * PY)          // 8 pixel rows per block
#define TW (TILE_PW + 2*RAD)       // 72 half2 per row (288B, 8B-aligned)
#define TH (TILE_PH + 2*RAD)       // 16 rows

#define K2F 72.13475204444817f     /* 50 * log2(e) */

__device__ __forceinline__ __half2 ex2h2(__half2 x) {
    unsigned xu = *reinterpret_cast<unsigned*>(&x);
    unsigned yu;
    asm("ex2.approx.f16x2 %0, %1;" : "=r"(yu) : "r"(xu));
    return *reinterpret_cast<__half2*>(&yu);
}

__global__ __launch_bounds__(BX * BY, 8)
void bilateral_kernel(const float* __restrict__ img, float* __restrict__ out) {
    __shared__ __align__(16) __half2 tile[TH][TW];   // (v, v) duplicated

    const int tx = threadIdx.x;
    const int ty = threadIdx.y;
    const int bx0 = blockIdx.x * TILE_PW;
    const int by0 = blockIdx.y * TILE_PH;

    // ---- tile fill: reflect, convert to duplicated half2 ----
    #pragma unroll
    for (int r = ty; r < TH; r += BY) {
        int gy = by0 + r - RAD;
        gy = (gy < 0) ? -gy : ((gy >= IMG_H) ? (2 * IMG_H - 2 - gy) : gy);
        const float* __restrict__ src = img + (size_t)gy * IMG_W;
        #pragma unroll
        for (int c = tx; c < TW; c += BX) {
            int gx = bx0 + c - RAD;
            gx = (gx < 0) ? -gx : ((gx >= IMG_W) ? (2 * IMG_W - 2 - gx) : gx);
            tile[r][c] = __float2half2_rn(src[gx]);
        }
    }
    __syncthreads();

    const int cb  = tx * PX;   // even -> aligned LDS.64 window loads
    const int py0 = ty * PY;

    // spatial weights exp(-q/18), q = offset^2, offset 0..4
    const float SW[5] = {1.0f, 0.94605765f, 0.80073740f, 0.60653067f, 0.41111229f};

    __half2 swk2[9];                 // dup(exp(-(k-4)^2/18)) -- column term
    #pragma unroll
    for (int k = 0; k < 9; k++) {
        const int a = (k < 4) ? (4 - k) : (k - 4);
        swk2[k] = __float2half2_rn(SW[a]);
    }
    __half2 swr2[9];                 // (row term j=0, row term j=1), r = 1..8
    #pragma unroll
    for (int r = 1; r <= 8; r++) {
        const int a0 = (r < 4) ? (4 - r) : (r - 4);
        const int a1 = (r < 5) ? (5 - r) : (r - 5);
        swr2[r] = __halves2half2(__float2half_rn(SW[a0]), __float2half_rn(SW[a1]));
    }
    const __half2 swEdge = __float2half2_rn(0.41111229f);   // exp(-16/18)
    const __half2 nK2    = __float2half2_rn(-K2F);

    // centers (f16) for pixels p = j*2+i at tile[py0+4+j][cb+4+i]
    __half chv[4];
    #pragma unroll
    for (int j = 0; j < PY; j++)
        #pragma unroll
        for (int i = 0; i < PX; i++)
            chv[j * 2 + i] = __low2half(tile[py0 + RAD + j][cb + RAD + i]);

    const __half2 cv2[2] = { __halves2half2(chv[0], chv[2]),    // (j0,i) over (j1,i)
                             __halves2half2(chv[1], chv[3]) };
    const __half2 ce2[2] = { __halves2half2(chv[0], chv[1]),    // (j,i0) beside (j,i1)
                             __halves2half2(chv[2], chv[3]) };

    const __half2 z = __float2half2_rn(0.0f);
    __half2 vN2[2] = {z, z}, vD2[2] = {z, z};   // vertical pairs, per i
    __half2 eN2[2] = {z, z}, eD2[2] = {z, z};   // edge rows r=0 (j=0), r=9 (j=1)

    // window rows r = 0..9; pixel row j active iff j <= r <= j+8
    #pragma unroll
    for (int r = 0; r < 10; r++) {
        __half2 fh[10];
        const uint2* __restrict__ rp =
            reinterpret_cast<const uint2*>(&tile[py0 + r][cb]);
        #pragma unroll
        for (int q = 0; q < 5; q++) {
            const uint2 v = rp[q];
            fh[2 * q]     = *reinterpret_cast<const __half2*>(&v.x);
            fh[2 * q + 1] = *reinterpret_cast<const __half2*>(&v.y);
        }

        if (r == 0 || r == 9) {
            // one pixel row -> pair the two horizontal pixels
            const int e = (r == 0) ? 0 : 1;
            const __half2 ce = ce2[e];
            #pragma unroll
            for (int k = 0; k < 9; k++) {
                const __half2 win2 = __lows2half2(fh[k], fh[k + 1]); // (f[k],f[k+1])
                const __half2 d2 = __hsub2(win2, ce);
                const __half2 g2 = __hmul2(__hmul2(d2, nK2), d2);    // -K2*d^2
                const __half2 w2 = __hmul2(__hmul2(ex2h2(g2), swk2[k]), swEdge);
                eN2[e] = __hfma2(w2, d2, eN2[e]);
                eD2[e] = __hadd2(eD2[e], w2);
            }
        } else {
            // both pixel rows -> vertical pairs per column i (shared win)
            #pragma unroll
            for (int i = 0; i < PX; i++) {
                #pragma unroll
                for (int k = 0; k < 9; k++) {
                    const __half2 win2 = fh[i + k];                  // (win,win)
                    const __half2 d2 = __hsub2(win2, cv2[i]);
                    const __half2 g2 = __hmul2(__hmul2(d2, nK2), d2);
                    const __half2 w2 = __hmul2(__hmul2(ex2h2(g2), swk2[k]), swr2[r]);
                    vN2[i] = __hfma2(w2, d2, vN2[i]);
                    vD2[i] = __hadd2(vD2[i], w2);
                }
            }
        }
    }

    // epilogue: out = c + num_d/den  (f32)
    #pragma unroll
    for (int j = 0; j < PY; j++) {
        float o[PX];
        #pragma unroll
        for (int i = 0; i < PX; i++) {
            float n  = (j == 0) ? __low2float(vN2[i]) : __high2float(vN2[i]);
            float dd = (j == 0) ? __low2float(vD2[i]) : __high2float(vD2[i]);
            n  += (i == 0) ? __low2float(eN2[j]) : __high2float(eN2[j]);
            dd += (i == 0) ? __low2float(eD2[j]) : __high2float(eD2[j]);
            o[i] = __half2float(chv[j * 2 + i]) + __fdividef(n, dd);
        }
        float2 ov = make_float2(o[0], o[1]);
        *reinterpret_cast<float2*>(
            &out[(size_t)(by0 + py0 + j) * IMG_W + bx0 + cb]) = ov;
    }
}

extern "C" void kernel_launch(void* const* d_in, const int* in_sizes, int n_in,
                              void* d_out, int out_size) {
    const float* img = (const float*)d_in[0];
    float* out = (float*)d_out;
    dim3 block(BX, BY);
    dim3 grid(IMG_W / TILE_PW, IMG_H / TILE_PH);
    bilateral_kernel<<<grid, block>>>(img, out);
}

// round 16
// speedup vs baseline: 1.4627x; 1.2379x over previous
#include <cuda_runtime.h>
#include <cuda_fp16.h>

// Bilateral filter 9x9, sigma_s=3, sigma_r=0.1, reflect padding, 4096x4096 fp32.
//
// Round-16: R15 (279us) is HFMA2-pipe-bound (fma=88.2%, issue only 68%).
// Cut fma-pipe ops per pair-tap 7 -> ~5.2:
//  1. column spatial term folded into the exponent's HFMA2 addend:
//     g = d*(-K2*d) + Lsk[k]   (9 duplicated half2 constants, cheap)
//  2. row spatial term hoisted out of the k-loop: accumulate row sums
//     rn = sum(e*d), rd = sum(e), then num += swr*rn, den += swr*rd
//     (2 HFMA2 per row replaces 9 HMUL2).
// Everything else = R15: (win-c) difference form, out = c + num/den,
// duplicated-half2 tile, vertical pairing + horizontal edge pairing,
// 40.5 MUFU/px.

#define IMG_H 4096
#define IMG_W 4096
#define RAD 4
#define BX 32
#define BY 4
#define PX 2
#define PY 2
#define TILE_PW (BX * PX)          // 64 pixel cols per block
#define TILE_PH (BY * PY)          // 8 pixel rows per block
#define TW (TILE_PW + 2*RAD)       // 72 half2 per row (288B, 8B-aligned)
#define TH (TILE_PH + 2*RAD)       // 16 rows

#define K2F 72.13475204444817f     /* 50 * log2(e) */
#define L2E 1.4426950408889634f

__device__ __forceinline__ __half2 ex2h2(__half2 x) {
    unsigned xu = *reinterpret_cast<unsigned*>(&x);
    unsigned yu;
    asm("ex2.approx.f16x2 %0, %1;" : "=r"(yu) : "r"(xu));
    return *reinterpret_cast<__half2*>(&yu);
}

__global__ __launch_bounds__(BX * BY, 8)
void bilateral_kernel(const float* __restrict__ img, float* __restrict__ out) {
    __shared__ __align__(16) __half2 tile[TH][TW];   // (v, v) duplicated

    const int tx = threadIdx.x;
    const int ty = threadIdx.y;
    const int bx0 = blockIdx.x * TILE_PW;
    const int by0 = blockIdx.y * TILE_PH;

    // ---- tile fill: reflect, convert to duplicated half2 ----
    #pragma unroll
    for (int r = ty; r < TH; r += BY) {
        int gy = by0 + r - RAD;
        gy = (gy < 0) ? -gy : ((gy >= IMG_H) ? (2 * IMG_H - 2 - gy) : gy);
        const float* __restrict__ src = img + (size_t)gy * IMG_W;
        #pragma unroll
        for (int c = tx; c < TW; c += BX) {
            int gx = bx0 + c - RAD;
            gx = (gx < 0) ? -gx : ((gx >= IMG_W) ? (2 * IMG_W - 2 - gx) : gx);
            tile[r][c] = __float2half2_rn(src[gx]);
        }
    }
    __syncthreads();

    const int cb  = tx * PX;   // even -> aligned LDS.64 window loads
    const int py0 = ty * PY;

    // spatial weights exp(-q/18) and log2-domain column terms -(k-4)^2/18*log2e
    const float SW[5] = {1.0f, 0.94605765f, 0.80073740f, 0.60653067f, 0.41111229f};

    __half2 lsk2[9];                 // dup(-(k-4)^2/18 * log2(e))
    #pragma unroll
    for (int k = 0; k < 9; k++) {
        const int a = (k - 4) * (k - 4);
        lsk2[k] = __float2half2_rn(-(float)a * (L2E / 18.0f));
    }
    __half2 swr2[9];                 // (row weight j=0, row weight j=1), r=1..8
    #pragma unroll
    for (int r = 1; r <= 8; r++) {
        const int a0 = (r < 4) ? (4 - r) : (r - 4);
        const int a1 = (r < 5) ? (5 - r) : (r - 5);
        swr2[r] = __halves2half2(__float2half_rn(SW[a0]), __float2half_rn(SW[a1]));
    }
    const __half2 swEdge = __float2half2_rn(0.41111229f);   // exp(-16/18)
    const __half2 nK2    = __float2half2_rn(-K2F);

    // centers (f16) for pixels p = j*2+i at tile[py0+4+j][cb+4+i]
    __half chv[4];
    #pragma unroll
    for (int j = 0; j < PY; j++)
        #pragma unroll
        for (int i = 0; i < PX; i++)
            chv[j * 2 + i] = __low2half(tile[py0 + RAD + j][cb + RAD + i]);

    const __half2 cv2[2] = { __halves2half2(chv[0], chv[2]),
                             __halves2half2(chv[1], chv[3]) };
    const __half2 ce2[2] = { __halves2half2(chv[0], chv[1]),
                             __halves2half2(chv[2], chv[3]) };

    const __half2 z = __float2half2_rn(0.0f);
    __half2 vN2[2] = {z, z}, vD2[2] = {z, z};   // vertical pairs, per i
    __half2 eN2[2] = {z, z}, eD2[2] = {z, z};   // edge rows r=0 (j=0), r=9 (j=1)

    // window rows r = 0..9; pixel row j active iff j <= r <= j+8
    #pragma unroll
    for (int r = 0; r < 10; r++) {
        __half2 fh[10];
        const uint2* __restrict__ rp =
            reinterpret_cast<const uint2*>(&tile[py0 + r][cb]);
        #pragma unroll
        for (int q = 0; q < 5; q++) {
            const uint2 v = rp[q];
            fh[2 * q]     = *reinterpret_cast<const __half2*>(&v.x);
            fh[2 * q + 1] = *reinterpret_cast<const __half2*>(&v.y);
        }

        if (r == 0 || r == 9) {
            // one pixel row -> pair the two horizontal pixels
            const int e = (r == 0) ? 0 : 1;
            const __half2 ce = ce2[e];
            __half2 rn = z, rd = z;
            #pragma unroll
            for (int k = 0; k < 9; k++) {
                const __half2 win2 = __lows2half2(fh[k], fh[k + 1]);
                const __half2 d2 = __hsub2(win2, ce);
                const __half2 t2 = __hmul2(d2, nK2);
                const __half2 g2 = __hfma2(d2, t2, lsk2[k]);  // exp + col term
                const __half2 e2 = ex2h2(g2);
                rn = __hfma2(e2, d2, rn);
                rd = __hadd2(rd, e2);
            }
            eN2[e] = __hfma2(swEdge, rn, eN2[e]);   // row weight once per row
            eD2[e] = __hfma2(swEdge, rd, eD2[e]);
        } else {
            // both pixel rows -> vertical pairs per column i (shared win)
            #pragma unroll
            for (int i = 0; i < PX; i++) {
                __half2 rn = z, rd = z;
                #pragma unroll
                for (int k = 0; k < 9; k++) {
                    const __half2 d2 = __hsub2(fh[i + k], cv2[i]);
                    const __half2 t2 = __hmul2(d2, nK2);
                    const __half2 g2 = __hfma2(d2, t2, lsk2[k]);
                    const __half2 e2 = ex2h2(g2);
                    rn = __hfma2(e2, d2, rn);
                    rd = __hadd2(rd, e2);
                }
                vN2[i] = __hfma2(swr2[r], rn, vN2[i]);  // once per row per col
                vD2[i] = __hfma2(swr2[r], rd, vD2[i]);
            }
        }
    }

    // epilogue: out = c + num_d/den  (f32)
    #pragma unroll
    for (int j = 0; j < PY; j++) {
        float o[PX];
        #pragma unroll
        for (int i = 0; i < PX; i++) {
            float n  = (j == 0) ? __low2float(vN2[i]) : __high2float(vN2[i]);
            float dd = (j == 0) ? __low2float(vD2[i]) : __high2float(vD2[i]);
            n  += (i == 0) ? __low2float(eN2[j]) : __high2float(eN2[j]);
            dd += (i == 0) ? __low2float(eD2[j]) : __high2float(eD2[j]);
            o[i] = __half2float(chv[j * 2 + i]) + __fdividef(n, dd);
        }
        float2 ov = make_float2(o[0], o[1]);
        *reinterpret_cast<float2*>(
            &out[(size_t)(by0 + py0 + j) * IMG_W + bx0 + cb]) = ov;
    }
}

extern "C" void kernel_launch(void* const* d_in, const int* in_sizes, int n_in,
                              void* d_out, int out_size) {
    const float* img = (const float*)d_in[0];
    float* out = (float*)d_out;
    dim3 block(BX, BY);
    dim3 grid(IMG_W / TILE_PW, IMG_H / TILE_PH);
    bilateral_kernel<<<grid, block>>>(img, out);
}